// round 11
// baseline (speedup 1.0000x reference)
#include <cuda_runtime.h>
#include <cuda_bf16.h>
#include <cstdint>

#define MDIM  256
#define NHEAD 8
#define HDIM  32
#define SEQ   128
#define BATCH 2
#define P     (BATCH*SEQ*SEQ)   // 32768 positions
#define QKV_N (3*MDIM)          // 768

// ---------------- scratch (device globals; no cudaMalloc allowed) -----------
__device__ float g_qkv[(size_t)P * QKV_N];   // 100.7 MB
__device__ float g_mean[P];
__device__ float g_rstd[P];
__device__ float g_o[(size_t)P * MDIM];      // 33.6 MB
__device__ int   g_mask_is_u8;

// ---------------- mask dtype detector ---------------------------------------
__global__ void detect_mask_kernel(const int* __restrict__ m) {
    __shared__ int flag;
    if (threadIdx.x == 0) flag = 0;
    __syncthreads();
    for (int i = threadIdx.x; i < P / 4; i += 256) {
        int v = m[i];
        if (v != 0 && v != 1) flag = 1;
    }
    __syncthreads();
    if (threadIdx.x == 0) g_mask_is_u8 = flag;
}

// ---------------- LayerNorm statistics: one warp per 256-wide row -----------
__global__ void ln_stats_kernel(const float* __restrict__ x,
                                float* __restrict__ mean,
                                float* __restrict__ rstd) {
    int row = blockIdx.x * blockDim.y + threadIdx.y;
    const float* xr = x + (size_t)row * MDIM;
    float s = 0.f, s2 = 0.f;
    for (int i = threadIdx.x; i < MDIM; i += 32) {
        float v = xr[i];
        s += v; s2 += v * v;
    }
    #pragma unroll
    for (int o = 16; o; o >>= 1) {
        s  += __shfl_xor_sync(0xffffffffu, s, o);
        s2 += __shfl_xor_sync(0xffffffffu, s2, o);
    }
    if (threadIdx.x == 0) {
        float m   = s * (1.f / MDIM);
        float var = fmaxf(s2 * (1.f / MDIM) - m * m, 0.f);
        mean[row] = m;
        rstd[row] = rsqrtf(var + 1e-5f);
    }
}

// ---------------- bf16 split-precision tensor-core GEMM ----------------------
// C[m,n] = sum_k A[m,k] * B[n,k], fp32 in/out.
// x = hi + lo (both bf16); D = Ah*Bh + Ah*Bl + Al*Bh.
// BM=128, BN=128, BK=32; 256 threads = 8 warps (2x4), warp tile 64x32.
// Register-prefetch pipeline: tile t+1 global loads issue before tile t's MMAs.
#define GBM 128
#define GBN 128
#define GBK 32
#define WST 36                           // words per row (32 + 4 pad)

#define MMA_BF16(d, a, b) \
    asm volatile("mma.sync.aligned.m16n8k16.row.col.f32.bf16.bf16.f32 " \
        "{%0,%1,%2,%3}, {%4,%5,%6,%7}, {%8,%9}, {%0,%1,%2,%3};" \
        : "+f"(d[0]), "+f"(d[1]), "+f"(d[2]), "+f"(d[3]) \
        : "r"(a[0]), "r"(a[1]), "r"(a[2]), "r"(a[3]), "r"(b[0]), "r"(b[1]))

__device__ __forceinline__ uint2 split_pack2(float x, float y) {
    __nv_bfloat162 h = __float22bfloat162_rn(make_float2(x, y));
    float hx = __bfloat162float(__low2bfloat16(h));
    float hy = __bfloat162float(__high2bfloat16(h));
    __nv_bfloat162 l = __float22bfloat162_rn(make_float2(x - hx, y - hy));
    uint2 r;
    r.x = *(uint32_t*)&h;
    r.y = *(uint32_t*)&l;
    return r;
}

template<bool LN>
__global__ __launch_bounds__(256) void gemm_bf16x3_kernel(
    const float* __restrict__ A, const float* __restrict__ Bmat,
    float* __restrict__ C, int M, int N, int K, int nblk,
    const float* __restrict__ mean, const float* __restrict__ rstd,
    const float* __restrict__ gamma, const float* __restrict__ beta)
{
    __shared__ uint32_t As[128 * WST];
    __shared__ uint32_t Bs[128 * WST];

    const int tid  = threadIdx.x;
    const int lane = tid & 31;
    const int wid  = tid >> 5;
    const int gid  = lane >> 2;
    const int tig  = lane & 3;
    const int warp_m = (wid & 1) << 6;
    const int warp_n = (wid >> 1) << 5;
    const int bm = (blockIdx.x / nblk) * GBM;
    const int bn = (blockIdx.x % nblk) * GBN;

    float acc[4][4][4];
    #pragma unroll
    for (int i = 0; i < 4; i++)
        #pragma unroll
        for (int j = 0; j < 4; j++)
            #pragma unroll
            for (int r = 0; r < 4; r++) acc[i][j][r] = 0.f;

    const int lm = tid >> 3;             // 0..31 (row within 32-row segment)
    const int lk = (tid & 7) << 2;       // k offset 0,4,...,28

    float mu[4], rs[4];
    if (LN) {
        #pragma unroll
        for (int seg = 0; seg < 4; seg++) {
            mu[seg] = mean[bm + seg * 32 + lm];
            rs[seg] = rstd[bm + seg * 32 + lm];
        }
    }

    float4 ra[4], rb[4];
    // ---- prologue: load tile 0 (LN applied at load) ------------------------
    #pragma unroll
    for (int seg = 0; seg < 4; seg++) {
        int m = seg * 32 + lm;
        float4 v = *(const float4*)(A + (size_t)(bm + m) * K + lk);
        if (LN) {
            float4 g  = *(const float4*)(gamma + lk);
            float4 be = *(const float4*)(beta  + lk);
            v.x = (v.x - mu[seg]) * rs[seg] * g.x + be.x;
            v.y = (v.y - mu[seg]) * rs[seg] * g.y + be.y;
            v.z = (v.z - mu[seg]) * rs[seg] * g.z + be.z;
            v.w = (v.w - mu[seg]) * rs[seg] * g.w + be.w;
        }
        ra[seg] = v;
        rb[seg] = *(const float4*)(Bmat + (size_t)(bn + m) * K + lk);
    }

    const int NT = K / GBK;
    for (int t = 0; t < NT; t++) {
        // ---- convert + store current tile ---------------------------------
        #pragma unroll
        for (int seg = 0; seg < 4; seg++) {
            int m = seg * 32 + lm;
            uint2 p01 = split_pack2(ra[seg].x, ra[seg].y);
            uint2 p23 = split_pack2(ra[seg].z, ra[seg].w);
            *(uint4*)&As[m * WST + lk] = make_uint4(p01.x, p01.y, p23.x, p23.y);
            uint2 q01 = split_pack2(rb[seg].x, rb[seg].y);
            uint2 q23 = split_pack2(rb[seg].z, rb[seg].w);
            *(uint4*)&Bs[m * WST + lk] = make_uint4(q01.x, q01.y, q23.x, q23.y);
        }
        __syncthreads();

        // ---- prefetch next tile (overlaps with MMA section) ---------------
        if (t + 1 < NT) {
            int k0 = (t + 1) * GBK;
            #pragma unroll
            for (int seg = 0; seg < 4; seg++) {
                int m = seg * 32 + lm;
                float4 v = *(const float4*)(A + (size_t)(bm + m) * K + k0 + lk);
                if (LN) {
                    float4 g  = *(const float4*)(gamma + k0 + lk);
                    float4 be = *(const float4*)(beta  + k0 + lk);
                    v.x = (v.x - mu[seg]) * rs[seg] * g.x + be.x;
                    v.y = (v.y - mu[seg]) * rs[seg] * g.y + be.y;
                    v.z = (v.z - mu[seg]) * rs[seg] * g.z + be.z;
                    v.w = (v.w - mu[seg]) * rs[seg] * g.w + be.w;
                }
                ra[seg] = v;
                rb[seg] = *(const float4*)(Bmat + (size_t)(bn + m) * K + k0 + lk);
            }
        }

        // ---- MMA section ---------------------------------------------------
        #pragma unroll
        for (int ks = 0; ks < 2; ks++) {
            const int k2b = ks * 8;
            uint32_t aH[4][4], aL[4][4], bH[4][2], bL[4][2];
            #pragma unroll
            for (int mt = 0; mt < 4; mt++) {
                int r0 = warp_m + mt * 16 + gid;
                uint2 w0 = *(const uint2*)&As[(r0    ) * WST + 2 * (k2b + tig)];
                uint2 w1 = *(const uint2*)&As[(r0 + 8) * WST + 2 * (k2b + tig)];
                uint2 w2 = *(const uint2*)&As[(r0    ) * WST + 2 * (k2b + 4 + tig)];
                uint2 w3 = *(const uint2*)&As[(r0 + 8) * WST + 2 * (k2b + 4 + tig)];
                aH[mt][0] = w0.x; aL[mt][0] = w0.y;
                aH[mt][1] = w1.x; aL[mt][1] = w1.y;
                aH[mt][2] = w2.x; aL[mt][2] = w2.y;
                aH[mt][3] = w3.x; aL[mt][3] = w3.y;
            }
            #pragma unroll
            for (int nt = 0; nt < 4; nt++) {
                int nb = warp_n + nt * 8 + gid;
                uint2 w0 = *(const uint2*)&Bs[nb * WST + 2 * (k2b + tig)];
                uint2 w1 = *(const uint2*)&Bs[nb * WST + 2 * (k2b + 4 + tig)];
                bH[nt][0] = w0.x; bL[nt][0] = w0.y;
                bH[nt][1] = w1.x; bL[nt][1] = w1.y;
            }
            #pragma unroll
            for (int mt = 0; mt < 4; mt++)
                #pragma unroll
                for (int nt = 0; nt < 4; nt++) {
                    MMA_BF16(acc[mt][nt], aH[mt], bH[nt]);
                    MMA_BF16(acc[mt][nt], aH[mt], bL[nt]);
                    MMA_BF16(acc[mt][nt], aL[mt], bH[nt]);
                }
        }
        __syncthreads();
    }

    // ---- epilogue ----------------------------------------------------------
    #pragma unroll
    for (int mt = 0; mt < 4; mt++) {
        int r0 = bm + warp_m + mt * 16 + gid;
        #pragma unroll
        for (int nt = 0; nt < 4; nt++) {
            int c = bn + warp_n + nt * 8 + 2 * tig;
            *(float2*)&C[(size_t)r0 * N + c] =
                make_float2(acc[mt][nt][0], acc[mt][nt][1]);
            *(float2*)&C[(size_t)(r0 + 8) * N + c] =
                make_float2(acc[mt][nt][2], acc[mt][nt][3]);
        }
    }
}

// ---------------- axial rotary on q,k (first 32 channels only) --------------
__global__ void rotary_kernel(float* __restrict__ qkv) {
    int gid = blockIdx.x * blockDim.x + threadIdx.x;
    if (gid >= P * 16) return;
    int i = gid & 15;
    int p = gid >> 4;
    int y = p & 127;
    int x = (p >> 7) & 127;
    int j = (i < 8) ? i : (i - 8);
    float invf = expf(-(2.f * (float)j / 16.f) * logf(10000.f));
    float t = (i < 8) ? (-1.f + 2.f * (float)x / 127.f)
                      : (-1.f + 2.f * (float)y / 127.f);
    float th = t * invf;
    float c = cosf(th), sn = sinf(th);

    float* q = qkv + (size_t)p * QKV_N + 2 * i;
    float q0 = q[0], q1 = q[1];
    q[0] = q0 * c - q1 * sn;
    q[1] = q1 * c + q0 * sn;
    float* k = q + MDIM;
    float k0 = k[0], k1 = k[1];
    k[0] = k0 * c - k1 * sn;
    k[1] = k1 * c + k0 * sn;
}

// ---------------- attention: single pass, packed f32x2 FFMA2 math -----------
#define FMA2(d, a, b) \
    asm("fma.rn.f32x2 %0, %1, %2, %0;" : "+l"(d) : "l"(a), "l"(b))
#define MUL2(d, a, b) \
    asm("mul.rn.f32x2 %0, %1, %2;" : "=l"(d) : "l"(a), "l"(b))

__device__ __forceinline__ unsigned long long pk2(float x, float y) {
    return (unsigned long long)__float_as_uint(x)
         | ((unsigned long long)__float_as_uint(y) << 32);
}

__global__ __launch_bounds__(128) void attn_kernel(
    const float* __restrict__ qkv,
    const unsigned char* __restrict__ mask8,
    const int* __restrict__ mask32,
    float* __restrict__ o)
{
    __shared__ float4 Ks4[SEQ][8];
    __shared__ float4 Vs4[SEQ][8];
    __shared__ unsigned char msk[SEQ];

    int blk = blockIdx.x;
    int h = blk & 7;
    int x = (blk >> 3) & 127;
    int b = blk >> 10;
    int tid = threadIdx.x;
    int rowbase = (b * SEQ + x) * SEQ;

    for (int fi = tid; fi < SEQ * 8; fi += 128) {
        int row = fi >> 3, d4 = fi & 7;
        const float* base = qkv + (size_t)(rowbase + row) * QKV_N + h * HDIM + d4 * 4;
        Ks4[row][d4] = *(const float4*)(base + MDIM);
        Vs4[row][d4] = *(const float4*)(base + 2 * MDIM);
    }
    {
        size_t midx = (size_t)(b * SEQ + x) * SEQ + tid;
        msk[tid] = g_mask_is_u8 ? mask8[midx] : (unsigned char)mask32[midx];
    }

    const float scale = 0.17677669529663687f;  // 32^-0.5 folded into q
    unsigned long long q2[16];
    const float4* qp = (const float4*)(qkv + (size_t)(rowbase + tid) * QKV_N + h * HDIM);
    #pragma unroll
    for (int j = 0; j < 8; j++) {
        float4 v = qp[j];
        q2[2 * j]     = pk2(v.x * scale, v.y * scale);
        q2[2 * j + 1] = pk2(v.z * scale, v.w * scale);
    }
    __syncthreads();

    unsigned long long acc2[16];
    #pragma unroll
    for (int i = 0; i < 16; i++) acc2[i] = 0ull;
    float sum = 0.f;

    #pragma unroll 2
    for (int k = 0; k < SEQ; k++) {
        const ulonglong2* kr = (const ulonglong2*)&Ks4[k][0];
        unsigned long long s2 = 0ull;
        #pragma unroll
        for (int i = 0; i < 8; i++) {
            ulonglong2 w = kr[i];
            FMA2(s2, q2[2 * i],     w.x);
            FMA2(s2, q2[2 * i + 1], w.y);
        }
        float s = __uint_as_float((unsigned)(s2 & 0xffffffffull))
                + __uint_as_float((unsigned)(s2 >> 32));
        float p = msk[k] ? 0.f : __expf(s);
        sum += p;
        unsigned long long p2 = pk2(p, p);
        const ulonglong2* vr = (const ulonglong2*)&Vs4[k][0];
        #pragma unroll
        for (int i = 0; i < 8; i++) {
            ulonglong2 w = vr[i];
            FMA2(acc2[2 * i],     p2, w.x);
            FMA2(acc2[2 * i + 1], p2, w.y);
        }
    }

    float inv = 1.f / sum;
    unsigned long long inv2 = pk2(inv, inv);
    ulonglong2* op = (ulonglong2*)(o + (size_t)(rowbase + tid) * MDIM + h * HDIM);
    #pragma unroll
    for (int i = 0; i < 8; i++) {
        unsigned long long r0, r1;
        MUL2(r0, acc2[2 * i],     inv2);
        MUL2(r1, acc2[2 * i + 1], inv2);
        op[i] = make_ulonglong2(r0, r1);
    }
}

// ---------------- launch ----------------------------------------------------
extern "C" void kernel_launch(void* const* d_in, const int* in_sizes, int n_in,
                              void* d_out, int out_size) {
    const float* pair_act = nullptr;
    const void*  pair_mask = nullptr;
    const float* ln_gamma = nullptr;
    const float* ln_beta  = nullptr;
    const float* Wqkv = nullptr;
    const float* Wout = nullptr;
    for (int i = 0; i < n_in; i++) {
        int sz = in_sizes[i];
        if      (sz == P * MDIM)     pair_act  = (const float*)d_in[i];
        else if (sz == P)            pair_mask = d_in[i];
        else if (sz == QKV_N * MDIM) Wqkv      = (const float*)d_in[i];
        else if (sz == MDIM * MDIM)  Wout      = (const float*)d_in[i];
        else if (sz == MDIM) {
            if (!ln_gamma) ln_gamma = (const float*)d_in[i];
            else           ln_beta  = (const float*)d_in[i];
        }
    }
    float* out = (float*)d_out;

    float *qkv, *meanp, *rstdp, *op;
    cudaGetSymbolAddress((void**)&qkv,   g_qkv);
    cudaGetSymbolAddress((void**)&meanp, g_mean);
    cudaGetSymbolAddress((void**)&rstdp, g_rstd);
    cudaGetSymbolAddress((void**)&op,    g_o);

    detect_mask_kernel<<<1, 256>>>((const int*)pair_mask);

    ln_stats_kernel<<<P / 8, dim3(32, 8)>>>(pair_act, meanp, rstdp);

    {
        int nb = QKV_N / GBN;                      // 6
        gemm_bf16x3_kernel<true><<<(P / GBM) * nb, 256>>>(
            pair_act, Wqkv, qkv, P, QKV_N, MDIM, nb,
            meanp, rstdp, ln_gamma, ln_beta);
    }

    rotary_kernel<<<(P * 16) / 256, 256>>>(qkv);

    attn_kernel<<<BATCH * SEQ * NHEAD, 128>>>(
        qkv, (const unsigned char*)pair_mask, (const int*)pair_mask, op);

    {
        int nb = MDIM / GBN;                       // 2
        gemm_bf16x3_kernel<false><<<(P / GBM) * nb, 256>>>(
            op, Wout, out, P, MDIM, MDIM, nb,
            nullptr, nullptr, nullptr, nullptr);
    }
}

// round 13
// speedup vs baseline: 1.0474x; 1.0474x over previous
#include <cuda_runtime.h>
#include <cuda_bf16.h>
#include <cstdint>

#define MDIM  256
#define NHEAD 8
#define HDIM  32
#define SEQ   128
#define BATCH 2
#define P     (BATCH*SEQ*SEQ)   // 32768 positions
#define QKV_N (3*MDIM)          // 768

// ---------------- scratch (device globals; no cudaMalloc allowed) -----------
__device__ float g_qkv[(size_t)P * QKV_N];   // 100.7 MB
__device__ float g_mean[P];
__device__ float g_rstd[P];
__device__ float g_o[(size_t)P * MDIM];      // 33.6 MB
__device__ int   g_mask_is_u8;

// ---------------- mask dtype detector ---------------------------------------
__global__ void detect_mask_kernel(const int* __restrict__ m) {
    __shared__ int flag;
    if (threadIdx.x == 0) flag = 0;
    __syncthreads();
    for (int i = threadIdx.x; i < P / 4; i += 256) {
        int v = m[i];
        if (v != 0 && v != 1) flag = 1;
    }
    __syncthreads();
    if (threadIdx.x == 0) g_mask_is_u8 = flag;
}

// ---------------- LayerNorm statistics: one warp per 256-wide row -----------
__global__ void ln_stats_kernel(const float* __restrict__ x,
                                float* __restrict__ mean,
                                float* __restrict__ rstd) {
    int row = blockIdx.x * blockDim.y + threadIdx.y;
    const float* xr = x + (size_t)row * MDIM;
    float s = 0.f, s2 = 0.f;
    for (int i = threadIdx.x; i < MDIM; i += 32) {
        float v = xr[i];
        s += v; s2 += v * v;
    }
    #pragma unroll
    for (int o = 16; o; o >>= 1) {
        s  += __shfl_xor_sync(0xffffffffu, s, o);
        s2 += __shfl_xor_sync(0xffffffffu, s2, o);
    }
    if (threadIdx.x == 0) {
        float m   = s * (1.f / MDIM);
        float var = fmaxf(s2 * (1.f / MDIM) - m * m, 0.f);
        mean[row] = m;
        rstd[row] = rsqrtf(var + 1e-5f);
    }
}

// ---------------- bf16 split-precision tensor-core GEMM (R10 version) --------
// C[m,n] = sum_k A[m,k] * B[n,k], fp32 in/out.
// x = hi + lo (both bf16); D = Ah*Bh + Ah*Bl + Al*Bh.
// BM=128, BN=128, BK=32; 256 threads = 8 warps (2x4), warp tile 64x32.
#define GBM 128
#define GBN 128
#define GBK 32
#define WST 36                           // words per row (32 + 4 pad)

#define MMA_BF16(d, a, b) \
    asm volatile("mma.sync.aligned.m16n8k16.row.col.f32.bf16.bf16.f32 " \
        "{%0,%1,%2,%3}, {%4,%5,%6,%7}, {%8,%9}, {%0,%1,%2,%3};" \
        : "+f"(d[0]), "+f"(d[1]), "+f"(d[2]), "+f"(d[3]) \
        : "r"(a[0]), "r"(a[1]), "r"(a[2]), "r"(a[3]), "r"(b[0]), "r"(b[1]))

__device__ __forceinline__ uint2 split_pack2(float x, float y) {
    __nv_bfloat162 h = __float22bfloat162_rn(make_float2(x, y));
    float hx = __bfloat162float(__low2bfloat16(h));
    float hy = __bfloat162float(__high2bfloat16(h));
    __nv_bfloat162 l = __float22bfloat162_rn(make_float2(x - hx, y - hy));
    uint2 r;
    r.x = *(uint32_t*)&h;
    r.y = *(uint32_t*)&l;
    return r;
}

template<bool LN>
__global__ __launch_bounds__(256) void gemm_bf16x3_kernel(
    const float* __restrict__ A, const float* __restrict__ Bmat,
    float* __restrict__ C, int M, int N, int K, int nblk,
    const float* __restrict__ mean, const float* __restrict__ rstd,
    const float* __restrict__ gamma, const float* __restrict__ beta)
{
    __shared__ uint32_t As[128 * WST];
    __shared__ uint32_t Bs[128 * WST];

    const int tid  = threadIdx.x;
    const int lane = tid & 31;
    const int wid  = tid >> 5;
    const int gid  = lane >> 2;
    const int tig  = lane & 3;
    const int warp_m = (wid & 1) << 6;
    const int warp_n = (wid >> 1) << 5;
    const int bm = (blockIdx.x / nblk) * GBM;
    const int bn = (blockIdx.x % nblk) * GBN;

    float acc[4][4][4];
    #pragma unroll
    for (int i = 0; i < 4; i++)
        #pragma unroll
        for (int j = 0; j < 4; j++)
            #pragma unroll
            for (int r = 0; r < 4; r++) acc[i][j][r] = 0.f;

    const int lm = tid >> 3;             // row within 32-row segment
    const int lk = (tid & 7) << 2;       // k offset 0,4,...,28

    for (int k0 = 0; k0 < K; k0 += GBK) {
        #pragma unroll
        for (int seg = 0; seg < 4; seg++) {
            int m = seg * 32 + lm;
            float4 v = *(const float4*)(A + (size_t)(bm + m) * K + k0 + lk);
            if (LN) {
                float mu = mean[bm + m], rs = rstd[bm + m];
                float4 g  = *(const float4*)(gamma + k0 + lk);
                float4 be = *(const float4*)(beta  + k0 + lk);
                v.x = (v.x - mu) * rs * g.x + be.x;
                v.y = (v.y - mu) * rs * g.y + be.y;
                v.z = (v.z - mu) * rs * g.z + be.z;
                v.w = (v.w - mu) * rs * g.w + be.w;
            }
            uint2 p01 = split_pack2(v.x, v.y);
            uint2 p23 = split_pack2(v.z, v.w);
            *(uint4*)&As[m * WST + lk] = make_uint4(p01.x, p01.y, p23.x, p23.y);
        }
        #pragma unroll
        for (int seg = 0; seg < 4; seg++) {
            int n = seg * 32 + lm;
            float4 v = *(const float4*)(Bmat + (size_t)(bn + n) * K + k0 + lk);
            uint2 p01 = split_pack2(v.x, v.y);
            uint2 p23 = split_pack2(v.z, v.w);
            *(uint4*)&Bs[n * WST + lk] = make_uint4(p01.x, p01.y, p23.x, p23.y);
        }
        __syncthreads();

        #pragma unroll
        for (int ks = 0; ks < 2; ks++) {
            const int k2b = ks * 8;
            uint32_t aH[4][4], aL[4][4], bH[4][2], bL[4][2];
            #pragma unroll
            for (int mt = 0; mt < 4; mt++) {
                int r0 = warp_m + mt * 16 + gid;
                uint2 w0 = *(const uint2*)&As[(r0    ) * WST + 2 * (k2b + tig)];
                uint2 w1 = *(const uint2*)&As[(r0 + 8) * WST + 2 * (k2b + tig)];
                uint2 w2 = *(const uint2*)&As[(r0    ) * WST + 2 * (k2b + 4 + tig)];
                uint2 w3 = *(const uint2*)&As[(r0 + 8) * WST + 2 * (k2b + 4 + tig)];
                aH[mt][0] = w0.x; aL[mt][0] = w0.y;
                aH[mt][1] = w1.x; aL[mt][1] = w1.y;
                aH[mt][2] = w2.x; aL[mt][2] = w2.y;
                aH[mt][3] = w3.x; aL[mt][3] = w3.y;
            }
            #pragma unroll
            for (int nt = 0; nt < 4; nt++) {
                int nb = warp_n + nt * 8 + gid;
                uint2 w0 = *(const uint2*)&Bs[nb * WST + 2 * (k2b + tig)];
                uint2 w1 = *(const uint2*)&Bs[nb * WST + 2 * (k2b + 4 + tig)];
                bH[nt][0] = w0.x; bL[nt][0] = w0.y;
                bH[nt][1] = w1.x; bL[nt][1] = w1.y;
            }
            #pragma unroll
            for (int mt = 0; mt < 4; mt++)
                #pragma unroll
                for (int nt = 0; nt < 4; nt++) {
                    MMA_BF16(acc[mt][nt], aH[mt], bH[nt]);
                    MMA_BF16(acc[mt][nt], aH[mt], bL[nt]);
                    MMA_BF16(acc[mt][nt], aL[mt], bH[nt]);
                }
        }
        __syncthreads();
    }

    #pragma unroll
    for (int mt = 0; mt < 4; mt++) {
        int r0 = bm + warp_m + mt * 16 + gid;
        #pragma unroll
        for (int nt = 0; nt < 4; nt++) {
            int c = bn + warp_n + nt * 8 + 2 * tig;
            *(float2*)&C[(size_t)r0 * N + c] =
                make_float2(acc[mt][nt][0], acc[mt][nt][1]);
            *(float2*)&C[(size_t)(r0 + 8) * N + c] =
                make_float2(acc[mt][nt][2], acc[mt][nt][3]);
        }
    }
}

// ---------------- axial rotary on q,k (first 32 channels only) --------------
__global__ void rotary_kernel(float* __restrict__ qkv) {
    int gid = blockIdx.x * blockDim.x + threadIdx.x;
    if (gid >= P * 16) return;
    int i = gid & 15;
    int p = gid >> 4;
    int y = p & 127;
    int x = (p >> 7) & 127;
    int j = (i < 8) ? i : (i - 8);
    float invf = expf(-(2.f * (float)j / 16.f) * logf(10000.f));
    float t = (i < 8) ? (-1.f + 2.f * (float)x / 127.f)
                      : (-1.f + 2.f * (float)y / 127.f);
    float th = t * invf;
    float c = cosf(th), sn = sinf(th);

    float* q = qkv + (size_t)p * QKV_N + 2 * i;
    float q0 = q[0], q1 = q[1];
    q[0] = q0 * c - q1 * sn;
    q[1] = q1 * c + q0 * sn;
    float* k = q + MDIM;
    float k0 = k[0], k1 = k[1];
    k[0] = k0 * c - k1 * sn;
    k[1] = k1 * c + k0 * sn;
}

// ---------------- attention: single pass, packed f32x2 FFMA2 math -----------
#define FMA2(d, a, b) \
    asm("fma.rn.f32x2 %0, %1, %2, %0;" : "+l"(d) : "l"(a), "l"(b))
#define MUL2(d, a, b) \
    asm("mul.rn.f32x2 %0, %1, %2;" : "=l"(d) : "l"(a), "l"(b))

__device__ __forceinline__ unsigned long long pk2(float x, float y) {
    return (unsigned long long)__float_as_uint(x)
         | ((unsigned long long)__float_as_uint(y) << 32);
}

__global__ __launch_bounds__(128) void attn_kernel(
    const float* __restrict__ qkv,
    const unsigned char* __restrict__ mask8,
    const int* __restrict__ mask32,
    float* __restrict__ o)
{
    __shared__ float4 Ks4[SEQ][8];
    __shared__ float4 Vs4[SEQ][8];
    __shared__ unsigned char msk[SEQ];

    int blk = blockIdx.x;
    int h = blk & 7;
    int x = (blk >> 3) & 127;
    int b = blk >> 10;
    int tid = threadIdx.x;
    int rowbase = (b * SEQ + x) * SEQ;

    for (int fi = tid; fi < SEQ * 8; fi += 128) {
        int row = fi >> 3, d4 = fi & 7;
        const float* base = qkv + (size_t)(rowbase + row) * QKV_N + h * HDIM + d4 * 4;
        Ks4[row][d4] = *(const float4*)(base + MDIM);
        Vs4[row][d4] = *(const float4*)(base + 2 * MDIM);
    }
    {
        size_t midx = (size_t)(b * SEQ + x) * SEQ + tid;
        msk[tid] = g_mask_is_u8 ? mask8[midx] : (unsigned char)mask32[midx];
    }

    const float scale = 0.17677669529663687f;  // 32^-0.5 folded into q
    unsigned long long q2[16];
    const float4* qp = (const float4*)(qkv + (size_t)(rowbase + tid) * QKV_N + h * HDIM);
    #pragma unroll
    for (int j = 0; j < 8; j++) {
        float4 v = qp[j];
        q2[2 * j]     = pk2(v.x * scale, v.y * scale);
        q2[2 * j + 1] = pk2(v.z * scale, v.w * scale);
    }
    __syncthreads();

    unsigned long long acc2[16];
    #pragma unroll
    for (int i = 0; i < 16; i++) acc2[i] = 0ull;
    float sum = 0.f;

    #pragma unroll 2
    for (int k = 0; k < SEQ; k++) {
        const ulonglong2* kr = (const ulonglong2*)&Ks4[k][0];
        unsigned long long s2 = 0ull;
        #pragma unroll
        for (int i = 0; i < 8; i++) {
            ulonglong2 w = kr[i];
            FMA2(s2, q2[2 * i],     w.x);
            FMA2(s2, q2[2 * i + 1], w.y);
        }
        float s = __uint_as_float((unsigned)(s2 & 0xffffffffull))
                + __uint_as_float((unsigned)(s2 >> 32));
        float p = msk[k] ? 0.f : __expf(s);
        sum += p;
        unsigned long long p2 = pk2(p, p);
        const ulonglong2* vr = (const ulonglong2*)&Vs4[k][0];
        #pragma unroll
        for (int i = 0; i < 8; i++) {
            ulonglong2 w = vr[i];
            FMA2(acc2[2 * i],     p2, w.x);
            FMA2(acc2[2 * i + 1], p2, w.y);
        }
    }

    float inv = 1.f / sum;
    unsigned long long inv2 = pk2(inv, inv);
    ulonglong2* op = (ulonglong2*)(o + (size_t)(rowbase + tid) * MDIM + h * HDIM);
    #pragma unroll
    for (int i = 0; i < 8; i++) {
        unsigned long long r0, r1;
        MUL2(r0, acc2[2 * i],     inv2);
        MUL2(r1, acc2[2 * i + 1], inv2);
        op[i] = make_ulonglong2(r0, r1);
    }
}

// ---------------- launch ----------------------------------------------------
extern "C" void kernel_launch(void* const* d_in, const int* in_sizes, int n_in,
                              void* d_out, int out_size) {
    const float* pair_act = nullptr;
    const void*  pair_mask = nullptr;
    const float* ln_gamma = nullptr;
    const float* ln_beta  = nullptr;
    const float* Wqkv = nullptr;
    const float* Wout = nullptr;
    for (int i = 0; i < n_in; i++) {
        int sz = in_sizes[i];
        if      (sz == P * MDIM)     pair_act  = (const float*)d_in[i];
        else if (sz == P)            pair_mask = d_in[i];
        else if (sz == QKV_N * MDIM) Wqkv      = (const float*)d_in[i];
        else if (sz == MDIM * MDIM)  Wout      = (const float*)d_in[i];
        else if (sz == MDIM) {
            if (!ln_gamma) ln_gamma = (const float*)d_in[i];
            else           ln_beta  = (const float*)d_in[i];
        }
    }
    float* out = (float*)d_out;

    float *qkv, *meanp, *rstdp, *op;
    cudaGetSymbolAddress((void**)&qkv,   g_qkv);
    cudaGetSymbolAddress((void**)&meanp, g_mean);
    cudaGetSymbolAddress((void**)&rstdp, g_rstd);
    cudaGetSymbolAddress((void**)&op,    g_o);

    detect_mask_kernel<<<1, 256>>>((const int*)pair_mask);

    ln_stats_kernel<<<P / 8, dim3(32, 8)>>>(pair_act, meanp, rstdp);

    {
        int nb = QKV_N / GBN;                      // 6
        gemm_bf16x3_kernel<true><<<(P / GBM) * nb, 256>>>(
            pair_act, Wqkv, qkv, P, QKV_N, MDIM, nb,
            meanp, rstdp, ln_gamma, ln_beta);
    }

    rotary_kernel<<<(P * 16) / 256, 256>>>(qkv);

    attn_kernel<<<BATCH * SEQ * NHEAD, 128>>>(
        qkv, (const unsigned char*)pair_mask, (const int*)pair_mask, op);

    {
        int nb = MDIM / GBN;                       // 2
        gemm_bf16x3_kernel<false><<<(P / GBM) * nb, 256>>>(
            op, Wout, out, P, MDIM, MDIM, nb,
            nullptr, nullptr, nullptr, nullptr);
    }
}